// round 16
// baseline (speedup 1.0000x reference)
#include <cuda_runtime.h>
#include <cuda_fp16.h>
#include <stdint.h>

#define A_DIM 128
#define N_DIM 64
#define H_DIM 1024
#define NJOBS 2048

#define ZSTR 136   // fp16 elems per z row
#define FSTR 136   // filterbank row stride
#define TSTR2 72   // tT row stride

// ---------------- helpers ----------------
__device__ __forceinline__ uint32_t smem_u32(const void* p) {
    uint32_t a;
    asm("{ .reg .u64 t; cvta.to.shared.u64 t, %1; cvt.u32.u64 %0, t; }" : "=r"(a) : "l"(p));
    return a;
}
__device__ __forceinline__ uint32_t pkhf(float lo, float hi) {
    uint32_t r;
    asm("cvt.rn.f16x2.f32 %0, %1, %2;" : "=r"(r) : "f"(hi), "f"(lo));
    return r;
}
__device__ __forceinline__ void ldsm4(uint32_t a, uint32_t* r) {
    asm volatile("ldmatrix.sync.aligned.m8n8.x4.shared.b16 {%0,%1,%2,%3}, [%4];"
                 : "=r"(r[0]), "=r"(r[1]), "=r"(r[2]), "=r"(r[3]) : "r"(a));
}
__device__ __forceinline__ void ldsm4t(uint32_t a, uint32_t* r) {
    asm volatile("ldmatrix.sync.aligned.m8n8.x4.trans.shared.b16 {%0,%1,%2,%3}, [%4];"
                 : "=r"(r[0]), "=r"(r[1]), "=r"(r[2]), "=r"(r[3]) : "r"(a));
}
__device__ __forceinline__ void mma16816h(float* c, const uint32_t* a, const uint32_t* b) {
    asm volatile(
        "mma.sync.aligned.m16n8k16.row.col.f32.f16.f16.f32 "
        "{%0,%1,%2,%3}, {%4,%5,%6,%7}, {%8,%9}, {%0,%1,%2,%3};"
        : "+f"(c[0]), "+f"(c[1]), "+f"(c[2]), "+f"(c[3])
        : "r"(a[0]), "r"(a[1]), "r"(a[2]), "r"(a[3]), "r"(b[0]), "r"(b[1]));
}

// ---------------- SMEM layout (bytes) ----------------
#define SM_Z0   0          // 34816 each (z fp16)
#define SM_Z1   34816
#define SM_T0   69632      // 18432 each (tT fp16)
#define SM_T1   88064
#define SM_FY   106496     // 17408 each (fp16, single panel)
#define SM_FX   123904
#define SM_TOTAL 141312

__global__ __launch_bounds__(512, 1)
void filt_mma(const float* __restrict__ x, const float* __restrict__ xh,
              const float* __restrict__ hvec, const float* __restrict__ Ww,
              const float* __restrict__ Wb,
              float* __restrict__ out, int gridn) {
    extern __shared__ char sm[];
    __shared__ float s_par[5];
    __shared__ float s_red[32];
    __shared__ float s_inv[2];

    int tid = threadIdx.x;
    int wid = tid >> 5, lane = tid & 31;
    int grp = lane >> 3, li = lane & 7;
    int qt = lane >> 2;
    int qr = (lane & 3) * 2;

    // ======== prologue: params via warp-shuffle reductions ========
    if (wid < 5) {
        float p = 0.f;
        for (int j = lane; j < H_DIM; j += 32)
            p += __ldg(Ww + wid * H_DIM + j) * __ldg(hvec + j);
#pragma unroll
        for (int o = 16; o; o >>= 1) p += __shfl_xor_sync(0xFFFFFFFFu, p, o);
        if (lane == 0) s_par[wid] = p + __ldg(Wb + wid);
    }
    __syncthreads();

    float gX, gY, dd, i2v, gamma;
    {
        float var = expf(s_par[2] + 1e-8f);
        dd = expf(s_par[3]) * (float)(A_DIM - 1) / (float)(N_DIM - 1);
        gamma = expf(s_par[4]);
        gX = (float)(A_DIM + 1) * (s_par[0] + 1.f) * 0.5f;
        gY = (float)(A_DIM + 1) * (s_par[1] + 1.f) * 0.5f;
        i2v = 1.f / (2.f * var);
    }

    // pass 1: global sums
    {
        float sx = 0.f, sy = 0.f;
        for (int idx = tid; idx < N_DIM * A_DIM; idx += 512) {
            int n = idx >> 7, a = idx & 127;
            float off = ((float)n - (float)N_DIM * 0.5f - 0.5f) * dd;
            float da = (float)a - (gX + off);
            float db = (float)a - (gY + off);
            sx += expf(-da * da * i2v);
            sy += expf(-db * db * i2v);
        }
#pragma unroll
        for (int o = 16; o; o >>= 1) {
            sx += __shfl_xor_sync(0xFFFFFFFFu, sx, o);
            sy += __shfl_xor_sync(0xFFFFFFFFu, sy, o);
        }
        if (lane == 0) { s_red[wid] = sx; s_red[16 + wid] = sy; }
        __syncthreads();
        if (wid == 0) {
            float vx = (lane < 16) ? s_red[lane] : 0.f;
            float vy = (lane < 16) ? s_red[16 + lane] : 0.f;
#pragma unroll
            for (int o = 16; o; o >>= 1) {
                vx += __shfl_xor_sync(0xFFFFFFFFu, vx, o);
                vy += __shfl_xor_sync(0xFFFFFFFFu, vy, o);
            }
            if (lane == 0) { s_inv[0] = 1.f / vx; s_inv[1] = gamma / vy; }
        }
        __syncthreads();
    }
    float invX = s_inv[0], invYg = s_inv[1];

    // pass 2: fp16 filterbank panels (single precision term)
    for (int idx = tid; idx < N_DIM * A_DIM; idx += 512) {
        int n = idx >> 7, a = idx & 127;
        float off = ((float)n - (float)N_DIM * 0.5f - 0.5f) * dd;
        float da = (float)a - (gX + off);
        float db = (float)a - (gY + off);
        float fy = expf(-db * db * i2v) * invYg;
        float fx = expf(-da * da * i2v) * invX;

        uint32_t o = (uint32_t)((n * FSTR + a) * 2);
        *(__half*)(sm + SM_FY + o) = __float2half_rn(fy);
        *(__half*)(sm + SM_FX + o) = __float2half_rn(fx);
    }

    uint32_t sb = smem_u32(sm);
    int radd = (grp >> 1) * 8;
    int cadd = (grp & 1) * 8;

    bool is_compute = (wid < 8);
    int ltid = tid - 256;

    // loader: z(job) f32 -> fp16 panel at zbase. All 16 LDGs batched first
    // (guaranteed MLP=16), then convert+STS.
    auto ldz = [&](int job, uint32_t zbase) {
        const float* src = ((job >> 10) ? xh : x) + (size_t)(job & 1023) * (A_DIM * A_DIM);
        const float4* s4 = (const float4*)src;
        float4 v[16];
#pragma unroll
        for (int i = 0; i < 16; i++) v[i] = __ldg(s4 + ltid + (i << 8));
#pragma unroll
        for (int i = 0; i < 16; i++) {
            int e4 = ltid + (i << 8);
            int e = e4 << 2;
            int a = e >> 7, b = e & 127;
            uint32_t hA = pkhf(v[i].x, v[i].y), hB = pkhf(v[i].z, v[i].w);
            *(uint2*)(sm + zbase + (uint32_t)((a * ZSTR + b) * 2)) = make_uint2(hA, hB);
        }
    };

    // ---- stage 1 mapping: 8 warps = 4 b-groups (32 cols) x 2 n-halves (32 n) ----
    int bg2 = wid & 3, nhh = wid >> 2;
    int b0 = bg2 * 32;
    uint32_t offA1p0 = (uint32_t)(((li + radd) * ZSTR + b0 + cadd) * 2);
    uint32_t offA1p1 = offA1p0 + 32;   // b0+16 (16 cols * 2B)
    uint32_t offB1[2];
#pragma unroll
    for (int q = 0; q < 2; q++)
        offB1[q] = (uint32_t)(((nhh * 32 + 16 * q + li + radd) * FSTR + cadd) * 2);

    // ---- stage 2 mapping: 8 warps = 4 n-strips (16 rows) x 2 m-halves (32) ----
    int n0 = (wid >> 1) * 16;
    int m0 = (wid & 1) * 32;
    uint32_t offA2 = (uint32_t)(((li + radd) * TSTR2 + n0 + cadd) * 2);
    uint32_t offB2[2];
#pragma unroll
    for (int q = 0; q < 2; q++)
        offB2[q] = (uint32_t)(((m0 + 16 * q + li + radd) * FSTR + cadd) * 2);

    int bx = blockIdx.x;
    int cnt = (NJOBS - bx + gridn - 1) / gridn;

    // prime z[0] with job 0
    if (!is_compute) ldz(bx, SM_Z0);
    __syncthreads();  // panels + z(0) visible

    for (int it = 0; it <= cnt; it++) {
        uint32_t zbase = (it & 1) ? SM_Z1 : SM_Z0;
        uint32_t tbase = (it & 1) ? SM_T1 : SM_T0;
        uint32_t tprev = (it & 1) ? SM_T0 : SM_T1;

        if (is_compute) {
            // ---- stage 1, job(it): tT[b][n] = sum_a z[a][b]*Fy[n][a] ----
            if (it < cnt) {
                float acc[2][4][4];
#pragma unroll
                for (int p = 0; p < 2; p++)
#pragma unroll
                    for (int j = 0; j < 4; j++)
#pragma unroll
                        for (int c = 0; c < 4; c++) acc[p][j][c] = 0.f;

#pragma unroll
                for (int s = 0; s < 8; s++) {
                    uint32_t Af[2][4], B[8];
                    uint32_t abase = (uint32_t)(s * 16 * ZSTR * 2);
                    ldsm4t(sb + zbase + offA1p0 + abase, Af[0]);
                    ldsm4t(sb + zbase + offA1p1 + abase, Af[1]);
#pragma unroll
                    for (int q = 0; q < 2; q++)
                        ldsm4(sb + SM_FY + offB1[q] + (uint32_t)(s * 32), B + 4 * q);
#pragma unroll
                    for (int p = 0; p < 2; p++)
#pragma unroll
                        for (int j = 0; j < 4; j++) mma16816h(acc[p][j], Af[p], B + 2 * j);
                }

                // write tT (fp16)
#pragma unroll
                for (int p = 0; p < 2; p++) {
                    int r0 = b0 + 16 * p + qt, r1 = r0 + 8;
#pragma unroll
                    for (int j = 0; j < 4; j++) {
                        int nj2 = nhh * 32 + 8 * j + qr;
                        *(uint32_t*)(sm + tbase + (r0 * TSTR2 + nj2) * 2) =
                            pkhf(acc[p][j][0], acc[p][j][1]);
                        *(uint32_t*)(sm + tbase + (r1 * TSTR2 + nj2) * 2) =
                            pkhf(acc[p][j][2], acc[p][j][3]);
                    }
                }
            }

            // ---- stage 2, job(it-1): C[n][m] = sum_b t[n][b]*Fx[m][b] ----
            if (it >= 1) {
                int job = bx + (it - 1) * gridn;
                int which = job >> 10;
                int img = job & 1023;

                float acc[4][4];
#pragma unroll
                for (int j = 0; j < 4; j++)
#pragma unroll
                    for (int c = 0; c < 4; c++) acc[j][c] = 0.f;

#pragma unroll
                for (int s = 0; s < 8; s++) {
                    uint32_t Af[4], B[8];
                    ldsm4t(sb + tprev + offA2 + (uint32_t)(s * 16 * TSTR2 * 2), Af);
#pragma unroll
                    for (int q = 0; q < 2; q++)
                        ldsm4(sb + SM_FX + offB2[q] + (uint32_t)(s * 32), B + 4 * q);
#pragma unroll
                    for (int j = 0; j < 4; j++) mma16816h(acc[j], Af, B + 2 * j);
                }

                float* ob = out + (size_t)img * (2 * N_DIM * N_DIM) + which * (N_DIM * N_DIM);
                int nA = n0 + qt, nB = nA + 8;
#pragma unroll
                for (int j = 0; j < 4; j++) {
                    int m = m0 + 8 * j + qr;
                    *(float2*)(ob + nA * N_DIM + m) = make_float2(acc[j][0], acc[j][1]);
                    *(float2*)(ob + nB * N_DIM + m) = make_float2(acc[j][2], acc[j][3]);
                }
            }
        } else if (it + 1 < cnt) {
            // ---- loader: z for job(it+1) into the other z buffer ----
            ldz(bx + (it + 1) * gridn, (it & 1) ? SM_Z0 : SM_Z1);
        }

        __syncthreads();  // seal: tT(it) for next stage2, z(it+1) for next stage1
    }
}

extern "C" void kernel_launch(void* const* d_in, const int* in_sizes, int n_in,
                              void* d_out, int out_size) {
    const float* x  = (const float*)d_in[0];
    const float* xh = (const float*)d_in[1];
    const float* h  = (const float*)d_in[2];
    const float* Ww = (const float*)d_in[3];
    const float* Wb = (const float*)d_in[4];
    float* out = (float*)d_out;

    int sms = 148;
    cudaDeviceGetAttribute(&sms, cudaDevAttrMultiProcessorCount, 0);
    if (sms <= 0) sms = 148;

    cudaFuncSetAttribute(filt_mma, cudaFuncAttributeMaxDynamicSharedMemorySize, SM_TOTAL);

    filt_mma<<<sms, 512, SM_TOTAL>>>(x, xh, h, Ww, Wb, out, sms);
}